// round 2
// baseline (speedup 1.0000x reference)
#include <cuda_runtime.h>

#define NB 64
#define NN 1024
#define NWORDS 32          // NN/32 bitmask words per node row
#define NITER 5

// scratch (no allocations allowed)
__device__ float g_feats[NB * NN];   // per-graph label histograms (6 stages accumulated)
__device__ float g_gram[NB * NB];    // unnormalized Gram

// -------------------------------------------------------------------------
// Kernel 1: one block per graph. Builds adjacency bitmask in SMEM, runs 5 WL
// iterations (seg/deg -> hash -> bitonic sort -> dense rank), accumulates the
// label histogram across all 6 label stages, writes feats to global.
// Dynamic SMEM layout (147456 bytes total, opt-in via cudaFuncSetAttribute):
//   [0      , 131072) : unsigned smask[32768]       adjacency bits (1024x1024)
//   [131072 , 135168) : int s_lab[1024]             labels (ALIASED as scan buf)
//   [135168 , 139264) : int s_cnt[1024]             histogram counts
//   [139264 , 147456) : u64 s_sort[1024]            sort keys (also K-reduce scratch)
// -------------------------------------------------------------------------
extern "C" __global__ void __launch_bounds__(1024, 1)
wl_kernel(const int* __restrict__ esrc, const int* __restrict__ edst,
          const int* __restrict__ labels0, const float* __restrict__ hw, int E)
{
    extern __shared__ unsigned char s_raw[];
    unsigned*            smask  = (unsigned*)s_raw;                        // 128KB
    int*                 s_lab  = (int*)(s_raw + 131072);                  // 4KB
    int*                 s_cnt  = (int*)(s_raw + 135168);                  // 4KB
    unsigned long long*  s_sort = (unsigned long long*)(s_raw + 139264);   // 8KB
    int*                 s_scan = s_lab;        // alias: scan runs when old labels dead
    int*                 s_red  = (int*)s_sort; // alias: used only before 1st sort

    const int t = threadIdx.x;
    const int b = blockIdx.x;
    const float w0 = hw[0], w1 = hw[1];

    // --- zero mask + counts (32768 words / 1024 threads = 32 each) ---
    #pragma unroll
    for (int w = 0; w < NWORDS; w++) smask[t + w * 1024] = 0u;
    s_cnt[t] = 0;
    __syncthreads();

    // --- build directed adjacency bitmask (atomicOr dedupes edges) ---
    for (int e = t; e < E; e += 1024) {
        int s = esrc[b * E + e];
        int d = edst[b * E + e];
        atomicOr(&smask[(s << 5) + (d >> 5)], 1u << (d & 31));
    }

    // --- initial labels + histogram stage 0 ---
    int lab = labels0[b * NN + t];
    s_lab[t] = lab;
    atomicAdd(&s_cnt[lab], 1);
    __syncthreads();

    // --- degree (constant across iterations), staggered so lanes hit distinct banks ---
    int deg = 0;
    #pragma unroll
    for (int wi = 0; wi < NWORDS; wi++) {
        int w = (wi + t) & 31;
        deg += __popc(smask[(t << 5) + w]);
    }

    // --- K = per-graph max degree (block reduce via s_sort scratch) ---
    int kv = deg;
    #pragma unroll
    for (int o = 16; o > 0; o >>= 1) kv = max(kv, __shfl_xor_sync(0xffffffffu, kv, o));
    if ((t & 31) == 0) s_red[t >> 5] = kv;
    __syncthreads();
    if (t < 32) {
        int v = s_red[t];
        #pragma unroll
        for (int o = 16; o > 0; o >>= 1) v = max(v, __shfl_xor_sync(0xffffffffu, v, o));
        if (t == 0) s_red[0] = v;
    }
    __syncthreads();
    const int K = s_red[0];
    __syncthreads();   // s_sort scratch free again before first sort

    const float Kw0 = __fmul_rn((float)K, w0);

    for (int it = 0; it < NITER; it++) {
        // --- seg = sum of out-neighbor labels (exact integer) ---
        int seg = 0;
        #pragma unroll
        for (int wi = 0; wi < NWORDS; wi++) {
            int w = (wi + t) & 31;
            unsigned m = smask[(t << 5) + w];
            int base = w << 5;
            while (m) {
                int bb = __ffs(m) - 1;
                m &= m - 1;
                seg += s_lab[base + bb];
            }
        }
        // --- hashed = (K*w0)*lab + w1*(seg+deg-K), no FMA contraction ---
        float h = __fadd_rn(__fmul_rn(Kw0, (float)s_lab[t]),
                            __fmul_rn(w1, (float)(seg + deg - K)));
        h = __fadd_rn(h, 0.0f);               // canonicalize -0 -> +0
        unsigned u = __float_as_uint(h);
        u = (u & 0x80000000u) ? ~u : (u | 0x80000000u);   // order-preserving map
        s_sort[t] = ((unsigned long long)u << 32) | (unsigned)t;
        __syncthreads();

        // --- bitonic sort of 1024 u64 (key<<32 | idx) ---
        for (int k = 2; k <= 1024; k <<= 1) {
            for (int j = k >> 1; j > 0; j >>= 1) {
                int ixj = t ^ j;
                if (ixj > t) {
                    unsigned long long a = s_sort[t];
                    unsigned long long c = s_sort[ixj];
                    bool asc = ((t & k) == 0);
                    if ((a > c) == asc) { s_sort[t] = c; s_sort[ixj] = a; }
                }
                __syncthreads();
            }
        }

        // --- dense ranks: flag boundaries, inclusive scan (Hillis-Steele) ---
        unsigned keyhi = (unsigned)(s_sort[t] >> 32);
        int flag = 0;
        if (t > 0) flag = (keyhi != (unsigned)(s_sort[t - 1] >> 32)) ? 1 : 0;
        __syncthreads();          // old labels fully consumed; safe to reuse alias
        s_scan[t] = flag;
        __syncthreads();
        for (int d = 1; d < 1024; d <<= 1) {
            int add = (t >= d) ? s_scan[t - d] : 0;
            __syncthreads();
            s_scan[t] += add;
            __syncthreads();
        }
        int rank = s_scan[t];
        int orig = (int)(unsigned)(s_sort[t] & 0xFFFFFFFFull);
        __syncthreads();          // all ranks read before scatter overwrites alias
        s_lab[orig] = rank;       // new labels
        atomicAdd(&s_cnt[rank], 1);
        __syncthreads();
    }

    g_feats[b * NN + t] = (float)s_cnt[t];
}

// -------------------------------------------------------------------------
// Kernel 2: Gram. Block b computes row b: dot(feats[b], feats[j]) for all j.
// feats[b] cached in SMEM; each of 8 warps handles 8 columns.
// -------------------------------------------------------------------------
extern "C" __global__ void __launch_bounds__(256)
gram_kernel()
{
    __shared__ float sf[NN];
    const int b = blockIdx.x;
    const int t = threadIdx.x;
    for (int i = t; i < NN; i += 256) sf[i] = g_feats[b * NN + i];
    __syncthreads();

    const int warp = t >> 5, lane = t & 31;
    for (int j = warp; j < NB; j += 8) {
        const float* fj = &g_feats[j * NN];
        float s = 0.0f;
        #pragma unroll 4
        for (int k = lane; k < NN; k += 32) s += sf[k] * fj[k];
        #pragma unroll
        for (int o = 16; o > 0; o >>= 1) s += __shfl_xor_sync(0xffffffffu, s, o);
        if (lane == 0) g_gram[b * NB + j] = s;
    }
}

// -------------------------------------------------------------------------
// Kernel 3: normalize by sqrt(diag) outer product.
// -------------------------------------------------------------------------
extern "C" __global__ void __launch_bounds__(64)
norm_kernel(float* __restrict__ out)
{
    const int i = blockIdx.x, j = threadIdx.x;
    float g  = g_gram[i * NB + j];
    float di = sqrtf(g_gram[i * NB + i]);
    float dj = sqrtf(g_gram[j * NB + j]);
    out[i * NB + j] = g / (di * dj);
}

extern "C" void kernel_launch(void* const* d_in, const int* in_sizes, int n_in,
                              void* d_out, int out_size)
{
    const int*   esrc = (const int*)d_in[0];
    const int*   edst = (const int*)d_in[1];
    const int*   lab  = (const int*)d_in[2];
    const float* hw   = (const float*)d_in[3];
    const int E = in_sizes[0] / NB;

    const size_t smem = 147456;  // 128K mask + 4K lab/scan + 4K cnt + 8K sort
    static bool attr_done = false;
    if (!attr_done) {
        cudaFuncSetAttribute(wl_kernel, cudaFuncAttributeMaxDynamicSharedMemorySize,
                             (int)smem);
        attr_done = true;
    }
    wl_kernel<<<NB, 1024, smem>>>(esrc, edst, lab, hw, E);
    gram_kernel<<<NB, 256>>>();
    norm_kernel<<<NB, NB>>>((float*)d_out);
}

// round 3
// speedup vs baseline: 1.3403x; 1.3403x over previous
#include <cuda_runtime.h>

#define NB 64
#define NN 1024
#define NWORDS 32          // NN/32 bitmask words per node row
#define NITER 5

typedef unsigned long long u64;

// scratch (no allocations allowed)
__device__ float g_feats[NB * NN];   // per-graph label histograms (6 stages accumulated)
__device__ float g_dnorm[NB];        // sqrt(dot(feats_b, feats_b))

// intra-warp bitonic merge: j = jstart..1, all partners within warp
__device__ __forceinline__ u64 warp_merge(u64 v, int t, int k, int jstart)
{
    bool dir = ((t & k) == 0);
    for (int j = jstart; j > 0; j >>= 1) {
        u64 o = __shfl_xor_sync(0xffffffffu, v, j);
        bool lower    = ((t & j) == 0);
        bool keep_min = (lower == dir);
        v = keep_min ? (v < o ? v : o) : (v > o ? v : o);
    }
    return v;
}

// -------------------------------------------------------------------------
// Kernel 1: one block per graph. Adjacency bitmask in SMEM, 5 WL iterations
// (seg/deg -> hash -> hybrid bitonic sort -> dense rank), histogram, feats
// + feature-vector norm. Dynamic SMEM layout (147456 B, opt-in):
//   [0      , 131072) : unsigned smask[32768]       adjacency bits (1024x1024)
//   [131072 , 135168) : int s_lab[1024]             labels
//   [135168 , 139264) : int s_cnt[1024]             histogram counts
//   [139264 , 147456) : u64 s_sort[1024]            sort keys
// -------------------------------------------------------------------------
extern "C" __global__ void __launch_bounds__(1024, 1)
wl_kernel(const int* __restrict__ esrc, const int* __restrict__ edst,
          const int* __restrict__ labels0, const float* __restrict__ hw, int E)
{
    extern __shared__ unsigned char s_raw[];
    unsigned* smask  = (unsigned*)s_raw;                   // 128KB
    int*      s_lab  = (int*)(s_raw + 131072);             // 4KB
    int*      s_cnt  = (int*)(s_raw + 135168);             // 4KB
    u64*      s_sort = (u64*)(s_raw + 139264);             // 8KB
    __shared__ int s_warp[32];                             // cross-warp scan/reduce

    const int t    = threadIdx.x;
    const int b    = blockIdx.x;
    const int lane = t & 31;
    const int wid  = t >> 5;
    const float w0 = hw[0], w1 = hw[1];

    // --- zero mask + counts ---
    #pragma unroll
    for (int w = 0; w < NWORDS; w++) smask[t + w * 1024] = 0u;
    s_cnt[t] = 0;
    __syncthreads();

    // --- build directed adjacency bitmask (atomicOr dedupes edges) ---
    for (int e = t; e < E; e += 1024) {
        int s = esrc[b * E + e];
        int d = edst[b * E + e];
        atomicOr(&smask[(s << 5) + (d >> 5)], 1u << (d & 31));
    }

    // --- initial labels + histogram stage 0 ---
    int lab0 = labels0[b * NN + t];
    s_lab[t] = lab0;
    atomicAdd(&s_cnt[lab0], 1);
    __syncthreads();

    // --- degree (constant), staggered word order -> conflict-free LDS ---
    int deg = 0;
    #pragma unroll
    for (int wi = 0; wi < NWORDS; wi++) {
        int w = (wi + t) & 31;
        deg += __popc(smask[(t << 5) + w]);
    }

    // --- K = per-graph max degree ---
    int kv = deg;
    #pragma unroll
    for (int o = 16; o > 0; o >>= 1) kv = max(kv, __shfl_xor_sync(0xffffffffu, kv, o));
    if (lane == 0) s_warp[wid] = kv;
    __syncthreads();
    if (t < 32) {
        int v = s_warp[t];
        #pragma unroll
        for (int o = 16; o > 0; o >>= 1) v = max(v, __shfl_xor_sync(0xffffffffu, v, o));
        if (t == 0) s_warp[0] = v;
    }
    __syncthreads();
    const int K = s_warp[0];
    __syncthreads();

    const float Kw0 = __fmul_rn((float)K, w0);

    for (int it = 0; it < NITER; it++) {
        // --- seg = sum of out-neighbor labels (exact integer) ---
        int seg = 0;
        #pragma unroll
        for (int wi = 0; wi < NWORDS; wi++) {
            int w = (wi + t) & 31;
            unsigned m = smask[(t << 5) + w];
            int base = w << 5;
            while (m) {
                int bb = __ffs(m) - 1;
                m &= m - 1;
                seg += s_lab[base + bb];
            }
        }
        // --- hashed = (K*w0)*lab + w1*(seg+deg-K), no FMA contraction ---
        float h = __fadd_rn(__fmul_rn(Kw0, (float)s_lab[t]),
                            __fmul_rn(w1, (float)(seg + deg - K)));
        h = __fadd_rn(h, 0.0f);               // canonicalize -0 -> +0
        unsigned u = __float_as_uint(h);
        u = (u & 0x80000000u) ? ~u : (u | 0x80000000u);   // order-preserving map
        u64 v = ((u64)u << 32) | (unsigned)t;

        // --- bitonic sort: k<=32 entirely in registers via shuffles ---
        #pragma unroll
        for (int k = 2; k <= 32; k <<= 1)
            v = warp_merge(v, t, k, k >> 1);

        s_sort[t] = v;
        __syncthreads();

        // --- k=64..1024: block stages (j>=32) in SMEM, tail (j<=16) via shfl ---
        #pragma unroll
        for (int k = 64; k <= 1024; k <<= 1) {
            for (int j = k >> 1; j >= 32; j >>= 1) {
                int ixj = t ^ j;
                if (ixj > t) {
                    u64 a = s_sort[t];
                    u64 c = s_sort[ixj];
                    bool asc = ((t & k) == 0);
                    if ((a > c) == asc) { s_sort[t] = c; s_sort[ixj] = a; }
                }
                __syncthreads();
            }
            v = s_sort[t];
            v = warp_merge(v, t, k, 16);
            s_sort[t] = v;
            __syncthreads();
        }

        // --- dense ranks: boundary flags + warp scan + cross-warp scan ---
        unsigned keyhi = (unsigned)(v >> 32);
        int flag = 0;
        if (t > 0) flag = (keyhi != (unsigned)(s_sort[t - 1] >> 32)) ? 1 : 0;

        int val = flag;
        #pragma unroll
        for (int o = 1; o < 32; o <<= 1) {
            int n = __shfl_up_sync(0xffffffffu, val, o);
            if (lane >= o) val += n;
        }
        if (lane == 31) s_warp[wid] = val;
        __syncthreads();
        if (t < 32) {
            int x = s_warp[t];
            #pragma unroll
            for (int o = 1; o < 32; o <<= 1) {
                int n = __shfl_up_sync(0xffffffffu, x, o);
                if (t >= o) x += n;
            }
            s_warp[t] = x;
        }
        __syncthreads();
        int rank = val + (wid > 0 ? s_warp[wid - 1] : 0);
        int orig = (int)(unsigned)(v & 0xFFFFFFFFull);

        s_lab[orig] = rank;               // permutation scatter: no race
        atomicAdd(&s_cnt[rank], 1);
        __syncthreads();
    }

    // --- feats + norm ---
    float c = (float)s_cnt[t];
    g_feats[b * NN + t] = c;

    float sq = c * c;
    #pragma unroll
    for (int o = 16; o > 0; o >>= 1) sq += __shfl_xor_sync(0xffffffffu, sq, o);
    if (lane == 0) s_warp[wid] = __float_as_int(sq);
    __syncthreads();
    if (t < 32) {
        float x = __int_as_float(s_warp[t]);
        #pragma unroll
        for (int o = 16; o > 0; o >>= 1) x += __shfl_xor_sync(0xffffffffu, x, o);
        if (t == 0) g_dnorm[b] = sqrtf(x);
    }
}

// -------------------------------------------------------------------------
// Kernel 2: normalized Gram. Block b computes row b (64 dots of length 1024),
// vectorized float4; normalization fused.
// -------------------------------------------------------------------------
extern "C" __global__ void __launch_bounds__(256)
gram_kernel(float* __restrict__ out)
{
    __shared__ float sf[NN];
    __shared__ float s_db;
    const int b = blockIdx.x;
    const int t = threadIdx.x;
    for (int i = t; i < NN; i += 256) sf[i] = g_feats[b * NN + i];
    if (t == 0) s_db = g_dnorm[b];
    __syncthreads();

    const int warp = t >> 5, lane = t & 31;
    const float4* sf4 = (const float4*)sf;
    const float db = s_db;
    for (int j = warp; j < NB; j += 8) {
        const float4* fj4 = (const float4*)&g_feats[j * NN];
        float s = 0.0f;
        #pragma unroll
        for (int k = lane; k < NN / 4; k += 32) {
            float4 a = sf4[k];
            float4 c = fj4[k];
            s += a.x * c.x + a.y * c.y + a.z * c.z + a.w * c.w;
        }
        #pragma unroll
        for (int o = 16; o > 0; o >>= 1) s += __shfl_xor_sync(0xffffffffu, s, o);
        if (lane == 0) out[b * NB + j] = s / (db * g_dnorm[j]);
    }
}

extern "C" void kernel_launch(void* const* d_in, const int* in_sizes, int n_in,
                              void* d_out, int out_size)
{
    const int*   esrc = (const int*)d_in[0];
    const int*   edst = (const int*)d_in[1];
    const int*   lab  = (const int*)d_in[2];
    const float* hw   = (const float*)d_in[3];
    const int E = in_sizes[0] / NB;

    const size_t smem = 147456;  // 128K mask + 4K lab + 4K cnt + 8K sort
    static bool attr_done = false;
    if (!attr_done) {
        cudaFuncSetAttribute(wl_kernel, cudaFuncAttributeMaxDynamicSharedMemorySize,
                             (int)smem);
        attr_done = true;
    }
    wl_kernel<<<NB, 1024, smem>>>(esrc, edst, lab, hw, E);
    gram_kernel<<<NB, 256>>>((float*)d_out);
}

// round 4
// speedup vs baseline: 1.6000x; 1.1938x over previous
#include <cuda_runtime.h>

#define NB 64
#define NN 1024
#define NWORDS 32          // NN/32 bitmask words per node row
#define NITER 5
#define ENTCAP 32768       // u16 neighbor-entry capacity (>= E)

typedef unsigned long long u64;

// scratch (no allocations allowed)
__device__ float g_feats[NB * NN];   // per-graph label histograms (6 stages)
__device__ float g_dnorm[NB];        // sqrt(dot(feats_b, feats_b))

// intra-warp bitonic merge on 32-bit keys: j = jstart..1 via shuffles
__device__ __forceinline__ unsigned warp_merge32(unsigned v, int t, int k, int jstart)
{
    bool dir = ((t & k) == 0);
    #pragma unroll
    for (int j = jstart; j > 0; j >>= 1) {
        unsigned o = __shfl_xor_sync(0xffffffffu, v, j);
        bool lower    = ((t & j) == 0);
        bool keep_min = (lower == dir);
        unsigned mn = v < o ? v : o;
        unsigned mx = v < o ? o : v;
        v = keep_min ? mn : mx;
    }
    return v;
}

// -------------------------------------------------------------------------
// Kernel 1: one block per graph.
// Phase A (once): adjacency bitmask (dedup) -> deg, K, CSR u16 neighbor lists.
// Phase B (x5):  seg gather -> hash -> 32-bit bitonic sort -> flag-scan ranks
//                -> per-thread binary-search rank lookup -> histogram.
// Dynamic SMEM layout (212992 B, opt-in):
//   [0      , 131072) : unsigned smask[32768]   adjacency bits (build only)
//   [131072 , 196608) : u16 s_ent[32768]        CSR neighbor entries
//   [196608 , 200704) : int s_lab[1024]         labels
//   [200704 , 204800) : int s_cnt[1024]         histogram counts
//   [204800 , 208896) : unsigned s_key[1024]    sort keys
//   [208896 , 212992) : int s_scan[1024]        rank per sorted position
// -------------------------------------------------------------------------
extern "C" __global__ void __launch_bounds__(1024, 1)
wl_kernel(const int* __restrict__ esrc, const int* __restrict__ edst,
          const int* __restrict__ labels0, const float* __restrict__ hw, int E)
{
    extern __shared__ unsigned char s_raw[];
    unsigned*       smask  = (unsigned*)s_raw;                 // 128KB
    unsigned short* s_ent  = (unsigned short*)(s_raw + 131072);// 64KB
    int*            s_lab  = (int*)(s_raw + 196608);           // 4KB
    int*            s_cnt  = (int*)(s_raw + 200704);           // 4KB
    unsigned*       s_key  = (unsigned*)(s_raw + 204800);      // 4KB
    int*            s_scan = (int*)(s_raw + 208896);           // 4KB
    __shared__ int s_warp[32];

    const int t    = threadIdx.x;
    const int b    = blockIdx.x;
    const int lane = t & 31;
    const int wid  = t >> 5;
    const float w0 = hw[0], w1 = hw[1];

    // --- zero mask + counts ---
    #pragma unroll
    for (int w = 0; w < NWORDS; w++) smask[t + w * 1024] = 0u;
    s_cnt[t] = 0;
    __syncthreads();

    // --- build directed adjacency bitmask (atomicOr dedupes edges) ---
    for (int e = t; e < E; e += 1024) {
        int s = esrc[b * E + e];
        int d = edst[b * E + e];
        atomicOr(&smask[(s << 5) + (d >> 5)], 1u << (d & 31));
    }

    // --- initial labels + histogram stage 0 ---
    int lab0 = labels0[b * NN + t];
    s_lab[t] = lab0;
    atomicAdd(&s_cnt[lab0], 1);
    __syncthreads();

    // --- degree (staggered word order -> conflict-free LDS) ---
    int deg = 0;
    #pragma unroll
    for (int wi = 0; wi < NWORDS; wi++) {
        int w = (wi + t) & 31;
        deg += __popc(smask[(t << 5) + w]);
    }

    // --- K = max degree, and exclusive scan of deg -> CSR offsets ---
    int kv = deg;
    #pragma unroll
    for (int o = 16; o > 0; o >>= 1) kv = max(kv, __shfl_xor_sync(0xffffffffu, kv, o));
    int incl = deg;
    #pragma unroll
    for (int o = 1; o < 32; o <<= 1) {
        int n = __shfl_up_sync(0xffffffffu, incl, o);
        if (lane >= o) incl += n;
    }
    if (lane == 31) { s_warp[wid] = incl; s_scan[wid] = kv; }  // s_scan low 32: warp maxes
    __syncthreads();
    int wpre = 0, kmax;
    {
        if (t < 32) {
            int x = s_warp[t];
            #pragma unroll
            for (int o = 1; o < 32; o <<= 1) {
                int n = __shfl_up_sync(0xffffffffu, x, o);
                if (t >= o) x += n;
            }
            s_warp[t] = x;
            int m = s_scan[t];
            #pragma unroll
            for (int o = 16; o > 0; o >>= 1) m = max(m, __shfl_xor_sync(0xffffffffu, m, o));
            if (t == 0) s_cnt[1023] = s_cnt[1023];  // no-op keep
            if (t == 0) s_scan[0] = m;              // overwritten later; read before
        }
        __syncthreads();
        wpre = (wid > 0) ? s_warp[wid - 1] : 0;
        kmax = s_scan[0];
        __syncthreads();
    }
    const int K = kmax;
    const int off = wpre + incl - deg;   // exclusive offset for thread t

    // --- build CSR u16 neighbor entries (once) ---
    {
        int p = off;
        #pragma unroll
        for (int w = 0; w < NWORDS; w++) {
            unsigned m = smask[(t << 5) + w];
            int base = w << 5;
            while (m) {
                int bb = __ffs(m) - 1;
                m &= m - 1;
                s_ent[p++] = (unsigned short)(base + bb);
            }
        }
    }
    __syncthreads();

    const float Kw0 = __fmul_rn((float)K, w0);

    for (int it = 0; it < NITER; it++) {
        // --- seg = sum of neighbor labels (exact integer), MLP via unroll ---
        int seg = 0;
        #pragma unroll 4
        for (int n = 0; n < deg; n++)
            seg += s_lab[s_ent[off + n]];

        // --- hashed = (K*w0)*lab + w1*(seg+deg-K), no FMA contraction ---
        float h = __fadd_rn(__fmul_rn(Kw0, (float)s_lab[t]),
                            __fmul_rn(w1, (float)(seg + deg - K)));
        h = __fadd_rn(h, 0.0f);               // canonicalize -0 -> +0
        unsigned u = __float_as_uint(h);
        u = (u & 0x80000000u) ? ~u : (u | 0x80000000u);   // order-preserving map
        const unsigned mykey = u;
        unsigned v = u;

        // --- bitonic sort (32-bit): k<=32 in registers via shuffles ---
        #pragma unroll
        for (int k = 2; k <= 32; k <<= 1)
            v = warp_merge32(v, t, k, k >> 1);
        s_key[t] = v;
        __syncthreads();

        // --- k=64..1024: SMEM stages (j>=32) + warp-shuffle tail (j<=16) ---
        #pragma unroll
        for (int k = 64; k <= 1024; k <<= 1) {
            for (int j = k >> 1; j >= 32; j >>= 1) {
                int ixj = t ^ j;
                if (ixj > t) {
                    unsigned a = s_key[t];
                    unsigned c = s_key[ixj];
                    bool asc = ((t & k) == 0);
                    if ((a > c) == asc) { s_key[t] = c; s_key[ixj] = a; }
                }
                __syncthreads();
            }
            v = s_key[t];
            v = warp_merge32(v, t, k, 16);
            s_key[t] = v;
            __syncthreads();
        }

        // --- rank per sorted position: boundary flag + block scan ---
        int flag = 0;
        if (t > 0) flag = (v != s_key[t - 1]) ? 1 : 0;
        int val = flag;
        #pragma unroll
        for (int o = 1; o < 32; o <<= 1) {
            int n = __shfl_up_sync(0xffffffffu, val, o);
            if (lane >= o) val += n;
        }
        if (lane == 31) s_warp[wid] = val;
        __syncthreads();
        if (t < 32) {
            int x = s_warp[t];
            #pragma unroll
            for (int o = 1; o < 32; o <<= 1) {
                int n = __shfl_up_sync(0xffffffffu, x, o);
                if (t >= o) x += n;
            }
            s_warp[t] = x;
        }
        __syncthreads();
        s_scan[t] = val + (wid > 0 ? s_warp[wid - 1] : 0);
        __syncthreads();

        // --- binary-search my key (pow-2 lower_bound, 10 LDS, no barriers) ---
        int lo = 0;
        #pragma unroll
        for (int s = 512; s > 0; s >>= 1)
            if (s_key[lo + s - 1] < mykey) lo += s;

        int rank = s_scan[lo];
        s_lab[t] = rank;                  // direct write, no scatter
        atomicAdd(&s_cnt[rank], 1);
        __syncthreads();
    }

    // --- feats + norm ---
    float c = (float)s_cnt[t];
    g_feats[b * NN + t] = c;

    float sq = c * c;
    #pragma unroll
    for (int o = 16; o > 0; o >>= 1) sq += __shfl_xor_sync(0xffffffffu, sq, o);
    if (lane == 0) s_warp[wid] = __float_as_int(sq);
    __syncthreads();
    if (t < 32) {
        float x = __int_as_float(s_warp[t]);
        #pragma unroll
        for (int o = 16; o > 0; o >>= 1) x += __shfl_xor_sync(0xffffffffu, x, o);
        if (t == 0) g_dnorm[b] = sqrtf(x);
    }
}

// -------------------------------------------------------------------------
// Kernel 2: normalized Gram. Grid (64, 8): block (b, jt) computes out[b][j]
// for j = jt*8 + warp (one dot of length 1024 per warp). 512 blocks.
// -------------------------------------------------------------------------
extern "C" __global__ void __launch_bounds__(256)
gram_kernel(float* __restrict__ out)
{
    __shared__ float sf[NN];
    const int b  = blockIdx.x;
    const int jt = blockIdx.y;
    const int t  = threadIdx.x;
    for (int i = t; i < NN; i += 256) sf[i] = g_feats[b * NN + i];
    __syncthreads();

    const int warp = t >> 5, lane = t & 31;
    const int j = jt * 8 + warp;
    const float4* sf4 = (const float4*)sf;
    const float4* fj4 = (const float4*)&g_feats[j * NN];
    float s = 0.0f;
    #pragma unroll
    for (int k = lane; k < NN / 4; k += 32) {
        float4 a = sf4[k];
        float4 c = fj4[k];
        s += a.x * c.x + a.y * c.y + a.z * c.z + a.w * c.w;
    }
    #pragma unroll
    for (int o = 16; o > 0; o >>= 1) s += __shfl_xor_sync(0xffffffffu, s, o);
    if (lane == 0) out[b * NB + j] = s / (g_dnorm[b] * g_dnorm[j]);
}

extern "C" void kernel_launch(void* const* d_in, const int* in_sizes, int n_in,
                              void* d_out, int out_size)
{
    const int*   esrc = (const int*)d_in[0];
    const int*   edst = (const int*)d_in[1];
    const int*   lab  = (const int*)d_in[2];
    const float* hw   = (const float*)d_in[3];
    const int E = in_sizes[0] / NB;

    const size_t smem = 212992;  // 128K mask + 64K entries + 4x4K arrays
    static bool attr_done = false;
    if (!attr_done) {
        cudaFuncSetAttribute(wl_kernel, cudaFuncAttributeMaxDynamicSharedMemorySize,
                             (int)smem);
        attr_done = true;
    }
    wl_kernel<<<NB, 1024, smem>>>(esrc, edst, lab, hw, E);
    gram_kernel<<<dim3(NB, 8), 256>>>((float*)d_out);
}

// round 5
// speedup vs baseline: 1.6538x; 1.0337x over previous
#include <cuda_runtime.h>

#define NB 64
#define NN 1024
#define NWORDS 32          // NN/32 bitmask words per node row
#define NITER 5

// scratch (no allocations allowed)
__device__ float g_feats[NB * NN];   // per-graph label histograms (6 stages)
__device__ float g_dnorm[NB];        // sqrt(dot(feats_b, feats_b))

// compare-exchange
__device__ __forceinline__ unsigned cex(unsigned a, unsigned b, bool keep_min)
{
    unsigned mn = a < b ? a : b;
    unsigned mx = a < b ? b : a;
    return keep_min ? mn : mx;
}

// one bitonic stage (merge size k, distance j) evaluated at position t
__device__ __forceinline__ unsigned stage_single(const unsigned* in, int t, int k, int j)
{
    bool asc = ((t & k) == 0);
    return cex(in[t], in[t ^ j], (((t & j) == 0) == asc));
}

// two consecutive stages (j1 then j2=j1/2) fused: 4 reads, 3 cex, result for slot t.
// Note ((t^j2)&j1)==(t&j1) and ((t^j2)&k)==(t&k), so both j1-results share predicates.
__device__ __forceinline__ unsigned stage_pair(const unsigned* in, int t, int k, int j1, int j2)
{
    bool asc = ((t & k) == 0);
    unsigned x0 = in[t];
    unsigned x1 = in[t ^ j1];
    unsigned y0 = in[t ^ j2];
    unsigned y1 = in[(t ^ j2) ^ j1];
    bool km1 = (((t & j1) == 0) == asc);
    unsigned a  = cex(x0, x1, km1);
    unsigned bb = cex(y0, y1, km1);
    return cex(a, bb, (((t & j2) == 0) == asc));
}

// intra-warp bitonic merge on 32-bit keys: j = jstart..1 via shuffles
__device__ __forceinline__ unsigned warp_merge32(unsigned v, int t, int k, int jstart)
{
    bool dir = ((t & k) == 0);
    #pragma unroll
    for (int j = jstart; j > 0; j >>= 1) {
        unsigned o = __shfl_xor_sync(0xffffffffu, v, j);
        bool keep_min = (((t & j) == 0) == dir);
        unsigned mn = v < o ? v : o;
        unsigned mx = v < o ? o : v;
        v = keep_min ? mn : mx;
    }
    return v;
}

// -------------------------------------------------------------------------
// Kernel 1: one block per graph.
// Phase A (once): adjacency bitmask (dedup) -> deg, K, CSR u16 neighbor lists.
// Phase B (x5):  seg gather -> hash -> stage-paired double-buffered bitonic
//                -> flag-scan ranks -> binary-search rank lookup -> histogram.
// Dynamic SMEM (217088 B, opt-in):
//   [0      , 131072) : unsigned smask[32768]   adjacency bits (build only)
//   [131072 , 196608) : u16 s_ent[32768]        CSR neighbor entries
//   [196608 , 200704) : int s_lab[1024]         labels
//   [200704 , 204800) : int s_cnt[1024]         histogram counts
//   [204800 , 208896) : unsigned s_keyA[1024]   sort ping buffer
//   [208896 , 212992) : unsigned s_keyB[1024]   sort pong buffer
//   [212992 , 217088) : int s_scan[1024]        rank per sorted position
// -------------------------------------------------------------------------
extern "C" __global__ void __launch_bounds__(1024, 1)
wl_kernel(const int* __restrict__ esrc, const int* __restrict__ edst,
          const int* __restrict__ labels0, const float* __restrict__ hw, int E)
{
    extern __shared__ unsigned char s_raw[];
    unsigned*       smask  = (unsigned*)s_raw;                  // 128KB
    unsigned short* s_ent  = (unsigned short*)(s_raw + 131072); // 64KB
    int*            s_lab  = (int*)(s_raw + 196608);            // 4KB
    int*            s_cnt  = (int*)(s_raw + 200704);            // 4KB
    unsigned*       s_keyA = (unsigned*)(s_raw + 204800);       // 4KB
    unsigned*       s_keyB = (unsigned*)(s_raw + 208896);       // 4KB
    int*            s_scan = (int*)(s_raw + 212992);            // 4KB
    __shared__ int s_warp[32];

    const int t    = threadIdx.x;
    const int b    = blockIdx.x;
    const int lane = t & 31;
    const int wid  = t >> 5;
    const float w0 = hw[0], w1 = hw[1];

    // --- zero mask + counts ---
    #pragma unroll
    for (int w = 0; w < NWORDS; w++) smask[t + w * 1024] = 0u;
    s_cnt[t] = 0;
    __syncthreads();

    // --- build directed adjacency bitmask (atomicOr dedupes edges) ---
    if ((E & 3) == 0) {
        const int4* s4 = (const int4*)(esrc + (size_t)b * E);
        const int4* d4 = (const int4*)(edst + (size_t)b * E);
        const int n4 = E >> 2;
        for (int i = t; i < n4; i += 1024) {
            int4 s = s4[i];
            int4 d = d4[i];
            atomicOr(&smask[(s.x << 5) + (d.x >> 5)], 1u << (d.x & 31));
            atomicOr(&smask[(s.y << 5) + (d.y >> 5)], 1u << (d.y & 31));
            atomicOr(&smask[(s.z << 5) + (d.z >> 5)], 1u << (d.z & 31));
            atomicOr(&smask[(s.w << 5) + (d.w >> 5)], 1u << (d.w & 31));
        }
    } else {
        for (int e = t; e < E; e += 1024) {
            int s = esrc[b * E + e];
            int d = edst[b * E + e];
            atomicOr(&smask[(s << 5) + (d >> 5)], 1u << (d & 31));
        }
    }

    // --- initial labels + histogram stage 0 ---
    int mylab = labels0[b * NN + t];
    s_lab[t] = mylab;
    atomicAdd(&s_cnt[mylab], 1);
    __syncthreads();

    // --- degree (staggered word order -> conflict-free LDS) ---
    int deg = 0;
    #pragma unroll
    for (int wi = 0; wi < NWORDS; wi++) {
        int w = (wi + t) & 31;
        deg += __popc(smask[(t << 5) + w]);
    }

    // --- K = max degree, exclusive scan of deg -> CSR offsets ---
    int kv = deg;
    #pragma unroll
    for (int o = 16; o > 0; o >>= 1) kv = max(kv, __shfl_xor_sync(0xffffffffu, kv, o));
    int incl = deg;
    #pragma unroll
    for (int o = 1; o < 32; o <<= 1) {
        int n = __shfl_up_sync(0xffffffffu, incl, o);
        if (lane >= o) incl += n;
    }
    if (lane == 31) { s_warp[wid] = incl; s_scan[wid] = kv; }
    __syncthreads();
    if (t < 32) {
        int x = s_warp[t];
        #pragma unroll
        for (int o = 1; o < 32; o <<= 1) {
            int n = __shfl_up_sync(0xffffffffu, x, o);
            if (t >= o) x += n;
        }
        s_warp[t] = x;
        int m = s_scan[t];
        #pragma unroll
        for (int o = 16; o > 0; o >>= 1) m = max(m, __shfl_xor_sync(0xffffffffu, m, o));
        if (t == 0) s_scan[0] = m;
    }
    __syncthreads();
    const int K   = s_scan[0];
    const int off = (wid > 0 ? s_warp[wid - 1] : 0) + incl - deg;
    __syncthreads();

    // --- build CSR u16 neighbor entries (once) ---
    {
        int p = off;
        #pragma unroll
        for (int w = 0; w < NWORDS; w++) {
            unsigned m = smask[(t << 5) + w];
            int base = w << 5;
            while (m) {
                int bb = __ffs(m) - 1;
                m &= m - 1;
                s_ent[p++] = (unsigned short)(base + bb);
            }
        }
    }
    __syncthreads();

    const float Kw0 = __fmul_rn((float)K, w0);

    for (int it = 0; it < NITER; it++) {
        // --- seg = sum of neighbor labels (exact integer) ---
        int seg = 0;
        #pragma unroll 4
        for (int n = 0; n < deg; n++)
            seg += s_lab[s_ent[off + n]];

        // --- hashed = (K*w0)*lab + w1*(seg+deg-K), no FMA contraction ---
        float h = __fadd_rn(__fmul_rn(Kw0, (float)mylab),
                            __fmul_rn(w1, (float)(seg + deg - K)));
        h = __fadd_rn(h, 0.0f);               // canonicalize -0 -> +0
        unsigned u = __float_as_uint(h);
        u = (u & 0x80000000u) ? ~u : (u | 0x80000000u);   // order-preserving map
        const unsigned mykey = u;
        unsigned v = u;

        // --- warp phase: k = 2..32 in registers ---
        #pragma unroll
        for (int k = 2; k <= 32; k <<= 1)
            v = warp_merge32(v, t, k, k >> 1);

        unsigned* cur = s_keyA;
        unsigned* nxt = s_keyB;
        cur[t] = v;
        __syncthreads();

        // --- k=64: j=32 + fused warp tail ---
        v = stage_single(cur, t, 64, 32);
        v = warp_merge32(v, t, 64, 16);
        nxt[t] = v; { unsigned* tmp = cur; cur = nxt; nxt = tmp; }
        __syncthreads();

        // --- k=128: pair(64,32) + tail ---
        v = stage_pair(cur, t, 128, 64, 32);
        v = warp_merge32(v, t, 128, 16);
        nxt[t] = v; { unsigned* tmp = cur; cur = nxt; nxt = tmp; }
        __syncthreads();

        // --- k=256: pair(128,64); single(32) + tail ---
        v = stage_pair(cur, t, 256, 128, 64);
        nxt[t] = v; { unsigned* tmp = cur; cur = nxt; nxt = tmp; }
        __syncthreads();
        v = stage_single(cur, t, 256, 32);
        v = warp_merge32(v, t, 256, 16);
        nxt[t] = v; { unsigned* tmp = cur; cur = nxt; nxt = tmp; }
        __syncthreads();

        // --- k=512: pair(256,128); pair(64,32) + tail ---
        v = stage_pair(cur, t, 512, 256, 128);
        nxt[t] = v; { unsigned* tmp = cur; cur = nxt; nxt = tmp; }
        __syncthreads();
        v = stage_pair(cur, t, 512, 64, 32);
        v = warp_merge32(v, t, 512, 16);
        nxt[t] = v; { unsigned* tmp = cur; cur = nxt; nxt = tmp; }
        __syncthreads();

        // --- k=1024: pair(512,256); pair(128,64); single(32) + tail ---
        v = stage_pair(cur, t, 1024, 512, 256);
        nxt[t] = v; { unsigned* tmp = cur; cur = nxt; nxt = tmp; }
        __syncthreads();
        v = stage_pair(cur, t, 1024, 128, 64);
        nxt[t] = v; { unsigned* tmp = cur; cur = nxt; nxt = tmp; }
        __syncthreads();
        v = stage_single(cur, t, 1024, 32);
        v = warp_merge32(v, t, 1024, 16);
        nxt[t] = v; { unsigned* tmp = cur; cur = nxt; nxt = tmp; }
        __syncthreads();
        // cur[] now holds fully sorted keys; v = cur[t]

        // --- rank per sorted position: boundary flag + block scan ---
        int flag = 0;
        if (t > 0) flag = (v != cur[t - 1]) ? 1 : 0;
        int val = flag;
        #pragma unroll
        for (int o = 1; o < 32; o <<= 1) {
            int n = __shfl_up_sync(0xffffffffu, val, o);
            if (lane >= o) val += n;
        }
        if (lane == 31) s_warp[wid] = val;
        __syncthreads();
        if (t < 32) {
            int x = s_warp[t];
            #pragma unroll
            for (int o = 1; o < 32; o <<= 1) {
                int n = __shfl_up_sync(0xffffffffu, x, o);
                if (t >= o) x += n;
            }
            s_warp[t] = x;
        }
        __syncthreads();
        s_scan[t] = val + (wid > 0 ? s_warp[wid - 1] : 0);
        __syncthreads();

        // --- binary-search my key (pow-2 lower_bound, barrier-free) ---
        int lo = 0;
        #pragma unroll
        for (int s = 512; s > 0; s >>= 1)
            if (cur[lo + s - 1] < mykey) lo += s;

        int rank = s_scan[lo];
        s_lab[t] = rank;
        mylab    = rank;
        atomicAdd(&s_cnt[rank], 1);
        __syncthreads();
    }

    // --- feats + norm ---
    float c = (float)s_cnt[t];
    g_feats[b * NN + t] = c;

    float sq = c * c;
    #pragma unroll
    for (int o = 16; o > 0; o >>= 1) sq += __shfl_xor_sync(0xffffffffu, sq, o);
    if (lane == 0) s_warp[wid] = __float_as_int(sq);
    __syncthreads();
    if (t < 32) {
        float x = __int_as_float(s_warp[t]);
        #pragma unroll
        for (int o = 16; o > 0; o >>= 1) x += __shfl_xor_sync(0xffffffffu, x, o);
        if (t == 0) g_dnorm[b] = sqrtf(x);
    }
}

// -------------------------------------------------------------------------
// Kernel 2: normalized Gram. Grid (64, 2) x 1024 threads: block (b, jt),
// warp w computes out[b][jt*32+w] (one 1024-dot per warp). 128 blocks.
// -------------------------------------------------------------------------
extern "C" __global__ void __launch_bounds__(1024)
gram_kernel(float* __restrict__ out)
{
    __shared__ float sf[NN];
    const int b  = blockIdx.x;
    const int jt = blockIdx.y;
    const int t  = threadIdx.x;
    sf[t] = g_feats[b * NN + t];
    __syncthreads();

    const int warp = t >> 5, lane = t & 31;
    const int j = jt * 32 + warp;
    const float4* sf4 = (const float4*)sf;
    const float4* fj4 = (const float4*)&g_feats[j * NN];
    float s = 0.0f;
    #pragma unroll
    for (int k = lane; k < NN / 4; k += 32) {
        float4 a = sf4[k];
        float4 c = fj4[k];
        s += a.x * c.x + a.y * c.y + a.z * c.z + a.w * c.w;
    }
    #pragma unroll
    for (int o = 16; o > 0; o >>= 1) s += __shfl_xor_sync(0xffffffffu, s, o);
    if (lane == 0) out[b * NB + j] = s / (g_dnorm[b] * g_dnorm[j]);
}

extern "C" void kernel_launch(void* const* d_in, const int* in_sizes, int n_in,
                              void* d_out, int out_size)
{
    const int*   esrc = (const int*)d_in[0];
    const int*   edst = (const int*)d_in[1];
    const int*   lab  = (const int*)d_in[2];
    const float* hw   = (const float*)d_in[3];
    const int E = in_sizes[0] / NB;

    const size_t smem = 217088;  // 128K mask + 64K ent + lab/cnt/keyA/keyB/scan
    static bool attr_done = false;
    if (!attr_done) {
        cudaFuncSetAttribute(wl_kernel, cudaFuncAttributeMaxDynamicSharedMemorySize,
                             (int)smem);
        attr_done = true;
    }
    wl_kernel<<<NB, 1024, smem>>>(esrc, edst, lab, hw, E);
    gram_kernel<<<dim3(NB, 2), 1024>>>((float*)d_out);
}